// round 13
// baseline (speedup 1.0000x reference)
#include <cuda_runtime.h>
#include <cuda_bf16.h>
#include <math.h>

// Inputs (metadata order):
//   d_in[0] predictions  float32 [B*S]  (B=1941, S=16384), row-major [B][S]
//   d_in[1] actuals      float32 [B*S]
//   d_in[2] indexes      int32   [S]
//   d_in[3] starts       int32   [N_SERIES=30490]
// Output: float32 scalar  sqrt( sum_{j,i: j>=starts[indexes[i]]} (p[j,i]-a[j,i])^2 / count )
//
// Single fused kernel (octet layout, full occupancy):
//   grid (8 stripes, 148 row-groups) = 1184 blocks; thread <-> fixed
//   8-column group; streams ~14 rows 2-row-unrolled; block-reduce to
//   g_partials. tid0 (sole per-block writer) does ONE release fence +
//   atomicInc(wrap); last block acquire-fences and finalizes in-kernel.
//   (R9's regression came from fencing ALL threads of every block.)

#define TPB        256
#define ROW_GROUPS 148
#define MAX_PART   4096
#define MAX_STRIPE 256

__device__ double       g_partials[MAX_PART];
__device__ long long    g_count_part[MAX_STRIPE];
__device__ unsigned int g_done;   // zero-init; atomicInc wraps -> replay-safe

__global__ __launch_bounds__(TPB, 4)
void octet_rmse_kernel(const float4* __restrict__ p,
                       const float4* __restrict__ a,
                       const int4*   __restrict__ indexes4,
                       const int*    __restrict__ starts,
                       float* __restrict__ out,
                       int B, int S4, int rows_per_grp)
{
    const int bx  = blockIdx.x;
    const int by  = blockIdx.y;
    const int tid = threadIdx.x;
    const int S8  = S4 >> 1;               // column-octets per row
    const int c8  = bx * TPB + tid;        // this thread's column-octet
    const bool active = (c8 < S8);

    __shared__ float     shf[TPB / 32];
    __shared__ long long shc[TPB / 32];
    const int lane = tid & 31, wid = tid >> 5, nwarps = TPB >> 5;

    // ---- per-thread gather of 8 starts (two int4 index loads) ----
    int st[8];
    #pragma unroll
    for (int k = 0; k < 8; ++k) st[k] = B;   // inactive: fully masked
    if (active) {
        int4 i0 = indexes4[c8 * 2];
        int4 i1 = indexes4[c8 * 2 + 1];
        st[0] = __ldg(&starts[i0.x]); st[1] = __ldg(&starts[i0.y]);
        st[2] = __ldg(&starts[i0.z]); st[3] = __ldg(&starts[i0.w]);
        st[4] = __ldg(&starts[i1.x]); st[5] = __ldg(&starts[i1.y]);
        st[6] = __ldg(&starts[i1.z]); st[7] = __ldg(&starts[i1.w]);
    }

    // ---- count partials (row-group 0 only; per-stripe; written by tid0) ----
    if (by == 0) {
        long long lc = 0;
        if (active) {
            #pragma unroll
            for (int k = 0; k < 8; ++k)
                lc += (long long)max(B - st[k], 0);
        }
        for (int off = 16; off > 0; off >>= 1)
            lc += __shfl_down_sync(0xFFFFFFFF, lc, off);
        if (lane == 0) shc[wid] = lc;
        __syncthreads();
        if (wid == 0) {
            long long v = (lane < nwarps) ? shc[lane] : 0;
            for (int off = 16; off > 0; off >>= 1)
                v += __shfl_down_sync(0xFFFFFFFF, v, off);
            if (lane == 0) g_count_part[bx] = v;
        }
    }

    // ---- masked sum of squares over this block's row range ----
    const int r0 = by * rows_per_grp;
    const int r1 = min(r0 + rows_per_grp, B);
    int minst = st[0];
    #pragma unroll
    for (int k = 1; k < 8; ++k) minst = min(minst, st[k]);
    int r = max(r0, minst);

    float acc = 0.0f;
    if (active && r < r1) {
        const int q0 = c8 * 2;             // first quad of this octet
        const float4* pp = p + (size_t)r * S4 + q0;
        const float4* aa = a + (size_t)r * S4 + q0;

        for (; r + 2 <= r1; r += 2) {
            float4 pA0 = pp[0],      pA1 = pp[1];
            float4 aA0 = aa[0],      aA1 = aa[1];
            float4 pB0 = pp[S4],     pB1 = pp[S4 + 1];
            float4 aB0 = aa[S4],     aB1 = aa[S4 + 1];
            pp += 2 * S4; aa += 2 * S4;

            float d;
            d = pA0.x - aA0.x; acc += (r     >= st[0]) ? d * d : 0.0f;
            d = pA0.y - aA0.y; acc += (r     >= st[1]) ? d * d : 0.0f;
            d = pA0.z - aA0.z; acc += (r     >= st[2]) ? d * d : 0.0f;
            d = pA0.w - aA0.w; acc += (r     >= st[3]) ? d * d : 0.0f;
            d = pA1.x - aA1.x; acc += (r     >= st[4]) ? d * d : 0.0f;
            d = pA1.y - aA1.y; acc += (r     >= st[5]) ? d * d : 0.0f;
            d = pA1.z - aA1.z; acc += (r     >= st[6]) ? d * d : 0.0f;
            d = pA1.w - aA1.w; acc += (r     >= st[7]) ? d * d : 0.0f;
            d = pB0.x - aB0.x; acc += (r + 1 >= st[0]) ? d * d : 0.0f;
            d = pB0.y - aB0.y; acc += (r + 1 >= st[1]) ? d * d : 0.0f;
            d = pB0.z - aB0.z; acc += (r + 1 >= st[2]) ? d * d : 0.0f;
            d = pB0.w - aB0.w; acc += (r + 1 >= st[3]) ? d * d : 0.0f;
            d = pB1.x - aB1.x; acc += (r + 1 >= st[4]) ? d * d : 0.0f;
            d = pB1.y - aB1.y; acc += (r + 1 >= st[5]) ? d * d : 0.0f;
            d = pB1.z - aB1.z; acc += (r + 1 >= st[6]) ? d * d : 0.0f;
            d = pB1.w - aB1.w; acc += (r + 1 >= st[7]) ? d * d : 0.0f;
        }
        for (; r < r1; ++r) {
            float4 p0 = pp[0], p1 = pp[1];
            float4 a0 = aa[0], a1 = aa[1];
            pp += S4; aa += S4;
            float d;
            d = p0.x - a0.x; acc += (r >= st[0]) ? d * d : 0.0f;
            d = p0.y - a0.y; acc += (r >= st[1]) ? d * d : 0.0f;
            d = p0.z - a0.z; acc += (r >= st[2]) ? d * d : 0.0f;
            d = p0.w - a0.w; acc += (r >= st[3]) ? d * d : 0.0f;
            d = p1.x - a1.x; acc += (r >= st[4]) ? d * d : 0.0f;
            d = p1.y - a1.y; acc += (r >= st[5]) ? d * d : 0.0f;
            d = p1.z - a1.z; acc += (r >= st[6]) ? d * d : 0.0f;
            d = p1.w - a1.w; acc += (r >= st[7]) ? d * d : 0.0f;
        }
    }

    // ---- block reduce sum -> g_partials (tid0 writes) ----
    for (int off = 16; off > 0; off >>= 1)
        acc += __shfl_down_sync(0xFFFFFFFF, acc, off);
    if (lane == 0) shf[wid] = acc;
    __syncthreads();
    if (wid == 0) {
        float v = (lane < nwarps) ? shf[lane] : 0.0f;
        for (int off = 16; off > 0; off >>= 1)
            v += __shfl_down_sync(0xFFFFFFFF, v, off);
        if (lane == 0)
            g_partials[by * gridDim.x + bx] = (double)v;
    }
    __syncthreads();   // tid0's fence below must follow the partial write

    // ---- last-block finalize: fences on ONE thread per block only ----
    __shared__ unsigned int s_rank;
    const unsigned int total = gridDim.x * gridDim.y;
    if (tid == 0) {
        __threadfence();                        // release g_partials/g_count
        s_rank = atomicInc(&g_done, total - 1); // wraps to 0 -> replay-safe
    }
    __syncthreads();
    if (s_rank == total - 1) {
        __threadfence();                        // acquire (one block, cheap)
        __syncthreads();
        __shared__ double    shs2[TPB / 32];
        __shared__ long long shc2[TPB / 32];
        const int nP = (int)total;
        double    s = 0.0;
        long long c = 0;
        for (int i = tid; i < nP; i += TPB)
            s += *((volatile double*)&g_partials[i]);
        for (int i = tid; i < (int)gridDim.x; i += TPB)
            c += *((volatile long long*)&g_count_part[i]);
        for (int off = 16; off > 0; off >>= 1) {
            s += __shfl_down_sync(0xFFFFFFFF, s, off);
            c += __shfl_down_sync(0xFFFFFFFF, c, off);
        }
        if (lane == 0) { shs2[wid] = s; shc2[wid] = c; }
        __syncthreads();
        if (wid == 0) {
            double    vs = (lane < nwarps) ? shs2[lane] : 0.0;
            long long vc = (lane < nwarps) ? shc2[lane] : 0;
            for (int off = 16; off > 0; off >>= 1) {
                vs += __shfl_down_sync(0xFFFFFFFF, vs, off);
                vc += __shfl_down_sync(0xFFFFFFFF, vc, off);
            }
            if (lane == 0)
                out[0] = (float)sqrt(vs / (double)vc);
        }
    }
}

extern "C" void kernel_launch(void* const* d_in, const int* in_sizes, int n_in,
                              void* d_out, int out_size)
{
    const float* predictions = (const float*)d_in[0];
    const float* actuals     = (const float*)d_in[1];
    const int*   indexes     = (const int*)d_in[2];
    const int*   starts      = (const int*)d_in[3];
    float*       out         = (float*)d_out;

    int n = in_sizes[0];          // B * S
    int S = in_sizes[2];          // 16384 (divisible by 8 for this dataset)
    int B = n / S;                // 1941
    int S4 = S / 4;               // 4096
    int S8 = S / 8;               // 2048 column-octets

    int stripes = (S8 + TPB - 1) / TPB;          // 8
    if (stripes > MAX_STRIPE) stripes = MAX_STRIPE;
    int row_groups = ROW_GROUPS;                 // 148 -> 1184 blocks
    while (stripes * row_groups > MAX_PART && row_groups > 1) row_groups--;
    if (row_groups > B) row_groups = B;
    int rows_per_grp = (B + row_groups - 1) / row_groups;   // 14

    dim3 grid(stripes, row_groups);
    octet_rmse_kernel<<<grid, TPB>>>((const float4*)predictions,
                                     (const float4*)actuals,
                                     (const int4*)indexes,
                                     starts, out, B, S4, rows_per_grp);
}

// round 14
// speedup vs baseline: 1.0425x; 1.0425x over previous
#include <cuda_runtime.h>
#include <cuda_bf16.h>
#include <math.h>

// Inputs (metadata order):
//   d_in[0] predictions  float32 [B*S]  (B=1941, S=16384), row-major [B][S]
//   d_in[1] actuals      float32 [B*S]
//   d_in[2] indexes      int32   [S]
//   d_in[3] starts       int32   [N_SERIES=30490]
// Output: float32 scalar  sqrt( sum_{j,i: j>=starts[indexes[i]]} (p[j,i]-a[j,i])^2 / count )
//
// Single fused kernel (octet layout, full occupancy):
//   grid (8 stripes, 148 row-groups) = 1184 blocks; thread <-> fixed
//   8-column group; streams ~14 rows 2-row-unrolled; block-reduce to
//   g_partials. tid0 (sole per-block writer) does ONE release fence +
//   atomicInc(wrap); last block acquire-fences and finalizes in-kernel.
//   (R9's regression came from fencing ALL threads of every block.)

#define TPB        256
#define ROW_GROUPS 148
#define MAX_PART   4096
#define MAX_STRIPE 256

__device__ double       g_partials[MAX_PART];
__device__ long long    g_count_part[MAX_STRIPE];
__device__ unsigned int g_done;   // zero-init; atomicInc wraps -> replay-safe

__global__ __launch_bounds__(TPB, 4)
void octet_rmse_kernel(const float4* __restrict__ p,
                       const float4* __restrict__ a,
                       const int4*   __restrict__ indexes4,
                       const int*    __restrict__ starts,
                       float* __restrict__ out,
                       int B, int S4, int rows_per_grp)
{
    const int bx  = blockIdx.x;
    const int by  = blockIdx.y;
    const int tid = threadIdx.x;
    const int S8  = S4 >> 1;               // column-octets per row
    const int c8  = bx * TPB + tid;        // this thread's column-octet
    const bool active = (c8 < S8);

    __shared__ float     shf[TPB / 32];
    __shared__ long long shc[TPB / 32];
    const int lane = tid & 31, wid = tid >> 5, nwarps = TPB >> 5;

    // ---- per-thread gather of 8 starts (two int4 index loads) ----
    int st[8];
    #pragma unroll
    for (int k = 0; k < 8; ++k) st[k] = B;   // inactive: fully masked
    if (active) {
        int4 i0 = indexes4[c8 * 2];
        int4 i1 = indexes4[c8 * 2 + 1];
        st[0] = __ldg(&starts[i0.x]); st[1] = __ldg(&starts[i0.y]);
        st[2] = __ldg(&starts[i0.z]); st[3] = __ldg(&starts[i0.w]);
        st[4] = __ldg(&starts[i1.x]); st[5] = __ldg(&starts[i1.y]);
        st[6] = __ldg(&starts[i1.z]); st[7] = __ldg(&starts[i1.w]);
    }

    // ---- count partials (row-group 0 only; per-stripe; written by tid0) ----
    if (by == 0) {
        long long lc = 0;
        if (active) {
            #pragma unroll
            for (int k = 0; k < 8; ++k)
                lc += (long long)max(B - st[k], 0);
        }
        for (int off = 16; off > 0; off >>= 1)
            lc += __shfl_down_sync(0xFFFFFFFF, lc, off);
        if (lane == 0) shc[wid] = lc;
        __syncthreads();
        if (wid == 0) {
            long long v = (lane < nwarps) ? shc[lane] : 0;
            for (int off = 16; off > 0; off >>= 1)
                v += __shfl_down_sync(0xFFFFFFFF, v, off);
            if (lane == 0) g_count_part[bx] = v;
        }
    }

    // ---- masked sum of squares over this block's row range ----
    const int r0 = by * rows_per_grp;
    const int r1 = min(r0 + rows_per_grp, B);
    int minst = st[0];
    #pragma unroll
    for (int k = 1; k < 8; ++k) minst = min(minst, st[k]);
    int r = max(r0, minst);

    float acc = 0.0f;
    if (active && r < r1) {
        const int q0 = c8 * 2;             // first quad of this octet
        const float4* pp = p + (size_t)r * S4 + q0;
        const float4* aa = a + (size_t)r * S4 + q0;

        for (; r + 2 <= r1; r += 2) {
            float4 pA0 = pp[0],      pA1 = pp[1];
            float4 aA0 = aa[0],      aA1 = aa[1];
            float4 pB0 = pp[S4],     pB1 = pp[S4 + 1];
            float4 aB0 = aa[S4],     aB1 = aa[S4 + 1];
            pp += 2 * S4; aa += 2 * S4;

            float d;
            d = pA0.x - aA0.x; acc += (r     >= st[0]) ? d * d : 0.0f;
            d = pA0.y - aA0.y; acc += (r     >= st[1]) ? d * d : 0.0f;
            d = pA0.z - aA0.z; acc += (r     >= st[2]) ? d * d : 0.0f;
            d = pA0.w - aA0.w; acc += (r     >= st[3]) ? d * d : 0.0f;
            d = pA1.x - aA1.x; acc += (r     >= st[4]) ? d * d : 0.0f;
            d = pA1.y - aA1.y; acc += (r     >= st[5]) ? d * d : 0.0f;
            d = pA1.z - aA1.z; acc += (r     >= st[6]) ? d * d : 0.0f;
            d = pA1.w - aA1.w; acc += (r     >= st[7]) ? d * d : 0.0f;
            d = pB0.x - aB0.x; acc += (r + 1 >= st[0]) ? d * d : 0.0f;
            d = pB0.y - aB0.y; acc += (r + 1 >= st[1]) ? d * d : 0.0f;
            d = pB0.z - aB0.z; acc += (r + 1 >= st[2]) ? d * d : 0.0f;
            d = pB0.w - aB0.w; acc += (r + 1 >= st[3]) ? d * d : 0.0f;
            d = pB1.x - aB1.x; acc += (r + 1 >= st[4]) ? d * d : 0.0f;
            d = pB1.y - aB1.y; acc += (r + 1 >= st[5]) ? d * d : 0.0f;
            d = pB1.z - aB1.z; acc += (r + 1 >= st[6]) ? d * d : 0.0f;
            d = pB1.w - aB1.w; acc += (r + 1 >= st[7]) ? d * d : 0.0f;
        }
        for (; r < r1; ++r) {
            float4 p0 = pp[0], p1 = pp[1];
            float4 a0 = aa[0], a1 = aa[1];
            pp += S4; aa += S4;
            float d;
            d = p0.x - a0.x; acc += (r >= st[0]) ? d * d : 0.0f;
            d = p0.y - a0.y; acc += (r >= st[1]) ? d * d : 0.0f;
            d = p0.z - a0.z; acc += (r >= st[2]) ? d * d : 0.0f;
            d = p0.w - a0.w; acc += (r >= st[3]) ? d * d : 0.0f;
            d = p1.x - a1.x; acc += (r >= st[4]) ? d * d : 0.0f;
            d = p1.y - a1.y; acc += (r >= st[5]) ? d * d : 0.0f;
            d = p1.z - a1.z; acc += (r >= st[6]) ? d * d : 0.0f;
            d = p1.w - a1.w; acc += (r >= st[7]) ? d * d : 0.0f;
        }
    }

    // ---- block reduce sum -> g_partials (tid0 writes) ----
    for (int off = 16; off > 0; off >>= 1)
        acc += __shfl_down_sync(0xFFFFFFFF, acc, off);
    if (lane == 0) shf[wid] = acc;
    __syncthreads();
    if (wid == 0) {
        float v = (lane < nwarps) ? shf[lane] : 0.0f;
        for (int off = 16; off > 0; off >>= 1)
            v += __shfl_down_sync(0xFFFFFFFF, v, off);
        if (lane == 0)
            g_partials[by * gridDim.x + bx] = (double)v;
    }
    __syncthreads();   // tid0's fence below must follow the partial write

    // ---- last-block finalize: fences on ONE thread per block only ----
    __shared__ unsigned int s_rank;
    const unsigned int total = gridDim.x * gridDim.y;
    if (tid == 0) {
        __threadfence();                        // release g_partials/g_count
        s_rank = atomicInc(&g_done, total - 1); // wraps to 0 -> replay-safe
    }
    __syncthreads();
    if (s_rank == total - 1) {
        __threadfence();                        // acquire (one block, cheap)
        __syncthreads();
        __shared__ double    shs2[TPB / 32];
        __shared__ long long shc2[TPB / 32];
        const int nP = (int)total;
        double    s = 0.0;
        long long c = 0;
        for (int i = tid; i < nP; i += TPB)
            s += *((volatile double*)&g_partials[i]);
        for (int i = tid; i < (int)gridDim.x; i += TPB)
            c += *((volatile long long*)&g_count_part[i]);
        for (int off = 16; off > 0; off >>= 1) {
            s += __shfl_down_sync(0xFFFFFFFF, s, off);
            c += __shfl_down_sync(0xFFFFFFFF, c, off);
        }
        if (lane == 0) { shs2[wid] = s; shc2[wid] = c; }
        __syncthreads();
        if (wid == 0) {
            double    vs = (lane < nwarps) ? shs2[lane] : 0.0;
            long long vc = (lane < nwarps) ? shc2[lane] : 0;
            for (int off = 16; off > 0; off >>= 1) {
                vs += __shfl_down_sync(0xFFFFFFFF, vs, off);
                vc += __shfl_down_sync(0xFFFFFFFF, vc, off);
            }
            if (lane == 0)
                out[0] = (float)sqrt(vs / (double)vc);
        }
    }
}

extern "C" void kernel_launch(void* const* d_in, const int* in_sizes, int n_in,
                              void* d_out, int out_size)
{
    const float* predictions = (const float*)d_in[0];
    const float* actuals     = (const float*)d_in[1];
    const int*   indexes     = (const int*)d_in[2];
    const int*   starts      = (const int*)d_in[3];
    float*       out         = (float*)d_out;

    int n = in_sizes[0];          // B * S
    int S = in_sizes[2];          // 16384 (divisible by 8 for this dataset)
    int B = n / S;                // 1941
    int S4 = S / 4;               // 4096
    int S8 = S / 8;               // 2048 column-octets

    int stripes = (S8 + TPB - 1) / TPB;          // 8
    if (stripes > MAX_STRIPE) stripes = MAX_STRIPE;
    int row_groups = ROW_GROUPS;                 // 148 -> 1184 blocks
    while (stripes * row_groups > MAX_PART && row_groups > 1) row_groups--;
    if (row_groups > B) row_groups = B;
    int rows_per_grp = (B + row_groups - 1) / row_groups;   // 14

    dim3 grid(stripes, row_groups);
    octet_rmse_kernel<<<grid, TPB>>>((const float4*)predictions,
                                     (const float4*)actuals,
                                     (const int4*)indexes,
                                     starts, out, B, S4, rows_per_grp);
}